// round 8
// baseline (speedup 1.0000x reference)
#include <cuda_runtime.h>
#include <math.h>
#include <stdint.h>

#define B_ 2
#define S_ 2048
#define D_ 1024
#define H_ 16
#define KH_ 4
#define HD_ 64
#define E_ 8
#define FF_ 2048
#define NTOK (B_*S_)
#define NSLOT (NTOK*2)
#define NEG_BIG -3.0e38f

#define BM 128
#define BN 128
#define LDA 36
#define LDB 136
#define PLANE (BM*LDA + 32*LDB)
#define SMEM_GEMM   (2*PLANE*4)
#define SMEM_GEMM_S (4*PLANE*4)
// attn smem: Qh,Ql[128][68], Kh,Kl[64][68], Vh,Vl[64][72], Ph,Pl[128][68]
#define SMEM_ATTN3 ((2*128*68 + 2*64*68 + 2*64*72 + 2*128*68)*4)

__device__ float g_xn  [NTOK*D_];
__device__ float g_q   [NTOK*H_*HD_];
__device__ float g_k   [NTOK*KH_*HD_];
__device__ float g_v   [NTOK*KH_*HD_];
__device__ float g_gate[NTOK*H_*HD_];
__device__ float g_x1  [NTOK*D_];
__device__ float g_xn2 [NTOK*D_];
__device__ float g_h   [(size_t)NSLOT*FF_];
__device__ float g_tmp [(size_t)NSLOT*D_];
__device__ int   g_topi[NTOK*2];
__device__ float g_topv[NTOK*2];
__device__ int   g_permTok[NSLOT];
__device__ float g_permW  [NSLOT];
__device__ int   g_tokSlot[NTOK*2];
__device__ int   g_counts[E_];
__device__ int   g_off   [E_+1];
__device__ int   g_cursor[E_];
__device__ float g_probsum[E_];

__device__ __forceinline__ unsigned f2tf(float v) {
    unsigned r; asm("cvt.rna.tf32.f32 %0, %1;" : "=r"(r) : "f"(v)); return r;
}
__device__ __forceinline__ void mma_tf32(float* d, const unsigned* a, unsigned b0, unsigned b1) {
    asm volatile("mma.sync.aligned.m16n8k8.row.col.f32.tf32.tf32.f32 "
        "{%0,%1,%2,%3}, {%4,%5,%6,%7}, {%8,%9}, {%0,%1,%2,%3};"
        : "+f"(d[0]), "+f"(d[1]), "+f"(d[2]), "+f"(d[3])
        : "r"(a[0]), "r"(a[1]), "r"(a[2]), "r"(a[3]), "r"(b0), "r"(b1));
}

// ======= tf32 MMA GEMM 128x128x32, double-buffered. EPI: 0 plain, 1 +X, 3 X[row]* =======
template<int EPI, bool SPLIT>
__device__ __forceinline__ void gemm_core(
    const float* __restrict__ A, const float* __restrict__ B,
    float* __restrict__ C, const float* __restrict__ X,
    int N, int K, int ldc, int rowstart, int rowend,
    const int* __restrict__ rowmap, int bx, int by)
{
    extern __shared__ float sm[];
    const int SS = PLANE * (SPLIT ? 2 : 1);
    int tid = threadIdx.x;
    int rowbase = rowstart + by*BM;
    if (rowbase >= rowend) return;
    int nbase = bx*BN;
    int k4 = tid & 7, n4 = tid & 31;
    const float* aP[4]; bool av[4];
#pragma unroll
    for (int i = 0; i < 4; i++) {
        int grow = rowbase + (tid >> 3) + 32*i;
        av[i] = grow < rowend;
        int ar = av[i] ? (rowmap ? rowmap[grow] : grow)
                       : (rowmap ? rowmap[rowstart] : rowstart);
        aP[i] = A + (size_t)ar*K + k4*4;
    }
    const float* bP = B + (size_t)(tid>>5)*N + nbase + n4*4;
    int lane = tid & 31, gp = lane >> 2, t4 = lane & 3;
    int w = tid >> 5, mb = (w & 3)*32, nb = (w >> 2)*64;

    float acc[2][8][4];
#pragma unroll
    for (int a = 0; a < 2; a++)
#pragma unroll
        for (int b = 0; b < 8; b++)
#pragma unroll
            for (int c = 0; c < 4; c++) acc[a][b][c] = 0.f;

    float4 va[4], vb[4];
#pragma unroll
    for (int i = 0; i < 4; i++) {
        va[i] = av[i] ? *(const float4*)aP[i] : make_float4(0,0,0,0);
        vb[i] = *(const float4*)(bP + (size_t)(8*i)*N);
    }
    int nkt = K >> 5;

    auto stage = [&](float* base) {
        float* Ah = base; float* Bh = base + BM*LDA;
        float* Al = Bh + 32*LDB; float* Bl = Al + BM*LDA;
#pragma unroll
        for (int i = 0; i < 4; i++) {
            int m = (tid >> 3) + 32*i;
            float vv[4] = {va[i].x, va[i].y, va[i].z, va[i].w};
            float4 hi, lo; float* hp = &hi.x; float* lp = &lo.x;
#pragma unroll
            for (int j = 0; j < 4; j++) {
                unsigned h2 = f2tf(vv[j]);
                hp[j] = __uint_as_float(h2);
                if (SPLIT) lp[j] = __uint_as_float(f2tf(vv[j] - __uint_as_float(h2)));
            }
            *(float4*)(Ah + m*LDA + k4*4) = hi;
            if (SPLIT) *(float4*)(Al + m*LDA + k4*4) = lo;
            int kr = (tid >> 5) + 8*i;
            float bv[4] = {vb[i].x, vb[i].y, vb[i].z, vb[i].w};
#pragma unroll
            for (int j = 0; j < 4; j++) {
                unsigned h2 = f2tf(bv[j]);
                hp[j] = __uint_as_float(h2);
                if (SPLIT) lp[j] = __uint_as_float(f2tf(bv[j] - __uint_as_float(h2)));
            }
            *(float4*)(Bh + kr*LDB + n4*4) = hi;
            if (SPLIT) *(float4*)(Bl + kr*LDB + n4*4) = lo;
        }
    };
    auto compute = [&](float* base) {
        float* Ah = base; float* Bh = base + BM*LDA;
        float* Al = Bh + 32*LDB; float* Bl = Al + BM*LDA;
#pragma unroll
        for (int ks = 0; ks < 4; ks++) {
            int kf = ks*8 + t4;
            unsigned a[2][4], al[2][4];
#pragma unroll
            for (int mt = 0; mt < 2; mt++) {
                int r = mb + mt*16 + gp;
                a[mt][0] = __float_as_uint(Ah[r*LDA + kf]);
                a[mt][1] = __float_as_uint(Ah[(r+8)*LDA + kf]);
                a[mt][2] = __float_as_uint(Ah[r*LDA + kf + 4]);
                a[mt][3] = __float_as_uint(Ah[(r+8)*LDA + kf + 4]);
                if (SPLIT) {
                    al[mt][0] = __float_as_uint(Al[r*LDA + kf]);
                    al[mt][1] = __float_as_uint(Al[(r+8)*LDA + kf]);
                    al[mt][2] = __float_as_uint(Al[r*LDA + kf + 4]);
                    al[mt][3] = __float_as_uint(Al[(r+8)*LDA + kf + 4]);
                }
            }
#pragma unroll
            for (int nt = 0; nt < 8; nt++) {
                int c = nb + nt*8 + gp;
                unsigned b0 = __float_as_uint(Bh[kf*LDB + c]);
                unsigned b1 = __float_as_uint(Bh[(kf+4)*LDB + c]);
#pragma unroll
                for (int mt = 0; mt < 2; mt++) mma_tf32(acc[mt][nt], a[mt], b0, b1);
                if (SPLIT) {
                    unsigned c0 = __float_as_uint(Bl[kf*LDB + c]);
                    unsigned c1 = __float_as_uint(Bl[(kf+4)*LDB + c]);
#pragma unroll
                    for (int mt = 0; mt < 2; mt++) {
                        mma_tf32(acc[mt][nt], a[mt], c0, c1);
                        mma_tf32(acc[mt][nt], al[mt], b0, b1);
                    }
                }
            }
        }
    };

    stage(sm);
    __syncthreads();
    for (int kt = 0; kt < nkt; kt++) {
        if (kt + 1 < nkt) {
#pragma unroll
            for (int i = 0; i < 4; i++) {
                va[i] = av[i] ? *(const float4*)(aP[i] + (kt+1)*32) : make_float4(0,0,0,0);
                vb[i] = *(const float4*)(bP + (size_t)((kt+1)*32 + 8*i)*N);
            }
        }
        compute(sm + (kt & 1)*SS);
        if (kt + 1 < nkt) stage(sm + ((kt+1) & 1)*SS);
        __syncthreads();
    }
#pragma unroll
    for (int mt = 0; mt < 2; mt++) {
        int r0 = rowbase + mb + mt*16 + gp;
        int r1 = r0 + 8;
        float s0 = 0.f, s1 = 0.f;
        if (EPI == 3) {
            s0 = (r0 < rowend) ? X[r0] : 0.f;
            s1 = (r1 < rowend) ? X[r1] : 0.f;
        }
#pragma unroll
        for (int nt = 0; nt < 8; nt++) {
            int col = nbase + nb + nt*8 + t4*2;
            if (r0 < rowend) {
                float2 v = make_float2(acc[mt][nt][0], acc[mt][nt][1]);
                if (EPI == 1) { float2 xr = *(const float2*)(X + (size_t)r0*ldc + col); v.x += xr.x; v.y += xr.y; }
                if (EPI == 3) { v.x *= s0; v.y *= s0; }
                *(float2*)(C + (size_t)r0*ldc + col) = v;
            }
            if (r1 < rowend) {
                float2 v = make_float2(acc[mt][nt][2], acc[mt][nt][3]);
                if (EPI == 1) { float2 xr = *(const float2*)(X + (size_t)r1*ldc + col); v.x += xr.x; v.y += xr.y; }
                if (EPI == 3) { v.x *= s1; v.y *= s1; }
                *(float2*)(C + (size_t)r1*ldc + col) = v;
            }
        }
    }
}

template<int EPI, bool SPLIT>
__global__ void __launch_bounds__(256) gemm_plain(
    const float* __restrict__ A, const float* __restrict__ B,
    float* __restrict__ C, const float* __restrict__ X, int N, int K, int M)
{
    gemm_core<EPI,SPLIT>(A, B, C, X, N, K, N, 0, M, nullptr, blockIdx.x, blockIdx.y);
}

__global__ void __launch_bounds__(256) proj_gemm(
    const float* __restrict__ wq, const float* __restrict__ wk,
    const float* __restrict__ wv, const float* __restrict__ wg)
{
    int bx = blockIdx.x;
    const float* Bp; float* C; int N; int lbx;
    if (bx < 8)       { Bp = wq; C = g_q;    N = 1024; lbx = bx; }
    else if (bx < 10) { Bp = wk; C = g_k;    N = 256;  lbx = bx - 8; }
    else if (bx < 12) { Bp = wv; C = g_v;    N = 256;  lbx = bx - 10; }
    else              { Bp = wg; C = g_gate; N = 1024; lbx = bx - 12; }
    gemm_core<0,true>(g_xn, Bp, C, nullptr, N, 1024, N, 0, NTOK, nullptr, lbx, blockIdx.y);
}

// ======= fused MoE w1+w3 GEMM with silu-mul epilogue (plain tf32) =======
// Each block: 128 rows x 64 cols of BOTH h1 and h3; writes silu(h1)*h3 -> g_h.
__global__ void __launch_bounds__(256) moe13_fused(
    const float* __restrict__ w1, const float* __restrict__ w3)
{
    extern __shared__ float sm[];
    int e = blockIdx.z;
    int rowstart = g_off[e], rowend = g_off[e+1];
    int rowbase = rowstart + blockIdx.y*BM;
    if (rowbase >= rowend) return;
    int tid = threadIdx.x;
    int nbase = blockIdx.x*64;
    int k4 = tid & 7;
    const float* aP[4]; bool av[4];
#pragma unroll
    for (int i = 0; i < 4; i++) {
        int grow = rowbase + (tid >> 3) + 32*i;
        av[i] = grow < rowend;
        int ar = av[i] ? g_permTok[grow] : g_permTok[rowstart];
        aP[i] = g_xn2 + (size_t)ar*D_ + k4*4;
    }
    int brow = tid >> 3;               // 0..31 (k within tile)
    int bcol = (tid & 7)*4;            // 0..28
    const float* b1P = w1 + (size_t)e*D_*FF_ + (size_t)brow*FF_ + nbase + bcol;
    const float* b3P = w3 + (size_t)e*D_*FF_ + (size_t)brow*FF_ + nbase + bcol;

    int lane = tid & 31, gp = lane >> 2, t4 = lane & 3;
    int w = tid >> 5, mb = (w & 3)*32, nb = (w >> 2)*32;

    float acc[2][2][4][4];   // [m13][mt][nt][4]
#pragma unroll
    for (int a = 0; a < 2; a++)
#pragma unroll
        for (int b = 0; b < 2; b++)
#pragma unroll
            for (int c = 0; c < 4; c++)
#pragma unroll
                for (int d = 0; d < 4; d++) acc[a][b][c][d] = 0.f;

    float4 va[4], v1a, v1b, v3a, v3b;
#pragma unroll
    for (int i = 0; i < 4; i++)
        va[i] = av[i] ? *(const float4*)aP[i] : make_float4(0,0,0,0);
    v1a = *(const float4*)b1P; v1b = *(const float4*)(b1P + 32);
    v3a = *(const float4*)b3P; v3b = *(const float4*)(b3P + 32);
    const int nkt = D_ >> 5;

    auto stage = [&](float* base) {
        float* Ah = base; float* Bh = base + BM*LDA;   // Bs[32][136]: w1 @0, w3 @68
#pragma unroll
        for (int i = 0; i < 4; i++) {
            int m = (tid >> 3) + 32*i;
            float vv[4] = {va[i].x, va[i].y, va[i].z, va[i].w};
            float4 hi; float* hp = &hi.x;
#pragma unroll
            for (int j = 0; j < 4; j++) hp[j] = __uint_as_float(f2tf(vv[j]));
            *(float4*)(Ah + m*LDA + k4*4) = hi;
        }
        float* brw = Bh + brow*LDB;
        float b1v[8] = {v1a.x,v1a.y,v1a.z,v1a.w, v1b.x,v1b.y,v1b.z,v1b.w};
        float b3v[8] = {v3a.x,v3a.y,v3a.z,v3a.w, v3b.x,v3b.y,v3b.z,v3b.w};
        float4 h0, h1;
        float* h0p = &h0.x; float* h1p = &h1.x;
#pragma unroll
        for (int j = 0; j < 4; j++) { h0p[j] = __uint_as_float(f2tf(b1v[j])); h1p[j] = __uint_as_float(f2tf(b1v[j+4])); }
        *(float4*)(brw + bcol) = h0;
        *(float4*)(brw + bcol + 32) = h1;
#pragma unroll
        for (int j = 0; j < 4; j++) { h0p[j] = __uint_as_float(f2tf(b3v[j])); h1p[j] = __uint_as_float(f2tf(b3v[j+4])); }
        *(float4*)(brw + 68 + bcol) = h0;
        *(float4*)(brw + 68 + bcol + 32) = h1;
    };
    auto compute = [&](float* base) {
        float* Ah = base; float* Bh = base + BM*LDA;
#pragma unroll
        for (int ks = 0; ks < 4; ks++) {
            int kf = ks*8 + t4;
            unsigned a[2][4];
#pragma unroll
            for (int mt = 0; mt < 2; mt++) {
                int r = mb + mt*16 + gp;
                a[mt][0] = __float_as_uint(Ah[r*LDA + kf]);
                a[mt][1] = __float_as_uint(Ah[(r+8)*LDA + kf]);
                a[mt][2] = __float_as_uint(Ah[r*LDA + kf + 4]);
                a[mt][3] = __float_as_uint(Ah[(r+8)*LDA + kf + 4]);
            }
#pragma unroll
            for (int m13 = 0; m13 < 2; m13++) {
#pragma unroll
                for (int nt = 0; nt < 4; nt++) {
                    int c = m13*68 + nb + nt*8 + gp;
                    unsigned b0 = __float_as_uint(Bh[kf*LDB + c]);
                    unsigned b1 = __float_as_uint(Bh[(kf+4)*LDB + c]);
                    mma_tf32(acc[m13][0][nt], a[0], b0, b1);
                    mma_tf32(acc[m13][1][nt], a[1], b0, b1);
                }
            }
        }
    };

    stage(sm);
    __syncthreads();
    for (int kt = 0; kt < nkt; kt++) {
        if (kt + 1 < nkt) {
            int ko = (kt+1)*32;
#pragma unroll
            for (int i = 0; i < 4; i++)
                va[i] = av[i] ? *(const float4*)(aP[i] + ko) : make_float4(0,0,0,0);
            v1a = *(const float4*)(b1P + (size_t)ko*FF_);
            v1b = *(const float4*)(b1P + (size_t)ko*FF_ + 32);
            v3a = *(const float4*)(b3P + (size_t)ko*FF_);
            v3b = *(const float4*)(b3P + (size_t)ko*FF_ + 32);
        }
        compute(sm + (kt & 1)*PLANE);
        if (kt + 1 < nkt) stage(sm + ((kt+1) & 1)*PLANE);
        __syncthreads();
    }
#pragma unroll
    for (int mt = 0; mt < 2; mt++) {
        int r0 = rowbase + mb + mt*16 + gp;
        int r1 = r0 + 8;
#pragma unroll
        for (int nt = 0; nt < 4; nt++) {
            int col = nbase + nb + nt*8 + t4*2;
            if (r0 < rowend) {
                float h1v0 = acc[0][mt][nt][0], h1v1 = acc[0][mt][nt][1];
                float h3v0 = acc[1][mt][nt][0], h3v1 = acc[1][mt][nt][1];
                float2 v;
                v.x = h1v0 / (1.f + __expf(-h1v0)) * h3v0;
                v.y = h1v1 / (1.f + __expf(-h1v1)) * h3v1;
                *(float2*)(g_h + (size_t)r0*FF_ + col) = v;
            }
            if (r1 < rowend) {
                float h1v0 = acc[0][mt][nt][2], h1v1 = acc[0][mt][nt][3];
                float h3v0 = acc[1][mt][nt][2], h3v1 = acc[1][mt][nt][3];
                float2 v;
                v.x = h1v0 / (1.f + __expf(-h1v0)) * h3v0;
                v.y = h1v1 / (1.f + __expf(-h1v1)) * h3v1;
                *(float2*)(g_h + (size_t)r1*FF_ + col) = v;
            }
        }
    }
}

__global__ void __launch_bounds__(256) moe2_gemm(const float* __restrict__ w2)
{
    int e = blockIdx.z;
    gemm_core<3,false>(g_h, w2 + (size_t)e*FF_*D_, g_tmp, g_permW, D_, FF_, D_,
                       g_off[e], g_off[e+1], nullptr, blockIdx.x, blockIdx.y);
}

// ======= rmsnorm =======
__global__ void rmsnorm_kernel(const float* __restrict__ x, const float* __restrict__ w,
                               float* __restrict__ out, float eps) {
    int t = blockIdx.x;
    const float4* xr = (const float4*)(x + (size_t)t * D_);
    float4 v = xr[threadIdx.x];
    float ss = v.x*v.x + v.y*v.y + v.z*v.z + v.w*v.w;
    __shared__ float smr[8];
    for (int o = 16; o > 0; o >>= 1) ss += __shfl_xor_sync(0xffffffffu, ss, o);
    if ((threadIdx.x & 31) == 0) smr[threadIdx.x >> 5] = ss;
    __syncthreads();
    if (threadIdx.x < 8) {
        float s2 = smr[threadIdx.x];
        for (int o = 4; o > 0; o >>= 1) s2 += __shfl_xor_sync(0xffu, s2, o);
        if (threadIdx.x == 0) smr[0] = s2;
    }
    __syncthreads();
    float sc = rsqrtf(smr[0] * (1.0f / D_) + eps);
    float4 wv = ((const float4*)w)[threadIdx.x];
    ((float4*)(out + (size_t)t * D_))[threadIdx.x] =
        make_float4(v.x*sc*wv.x, v.y*sc*wv.y, v.z*sc*wv.z, v.w*sc*wv.w);
}

// ======= q/k rmsnorm + rope =======
__global__ void qkrope_kernel(float* buf, const float* __restrict__ w, int nheads) {
    int wid = (blockIdx.x * blockDim.x + threadIdx.x) >> 5;
    int lane = threadIdx.x & 31;
    int t = wid / nheads, h = wid - t * nheads;
    int pos = t & (S_ - 1);
    size_t base = (size_t)t * nheads * HD_ + h * HD_;
    float v0 = buf[base + 2*lane], v1 = buf[base + 2*lane + 1];
    float ss = v0*v0 + v1*v1;
    for (int o = 16; o > 0; o >>= 1) ss += __shfl_xor_sync(0xffffffffu, ss, o);
    float sc = rsqrtf(ss * (1.0f / HD_) + 1e-5f);
    float a  = v0 * sc * w[2*lane];
    float b2 = v1 * sc * w[2*lane + 1];
    float inv = expf(-(float)lane * (2.0f / HD_) * 9.210340371976184f);
    float ang = (float)pos * inv;
    float cs = cosf(ang), sn = sinf(ang);
    buf[base + 2*lane]     = a*cs - b2*sn;
    buf[base + 2*lane + 1] = a*sn + b2*cs;
}

// ======= attention: split-tf32 MMA QK^T + PV, register m/l, fused gate =======
__global__ void __launch_bounds__(256) attn_tc2(
    const float* __restrict__ Q, const float* __restrict__ Kb,
    const float* __restrict__ Vb, float* __restrict__ G)
{
    extern __shared__ float sma[];
    float* Qh = sma;                  // [128][68]
    float* Ql = Qh + 128*68;
    float* Kh = Ql + 128*68;          // [64][68]
    float* Kl = Kh + 64*68;
    float* Vh = Kl + 64*68;           // [64][72]
    float* Vl = Vh + 64*72;
    float* Ph = Vl + 64*72;           // [128][68]
    float* Pl = Ph + 128*68;
    int qt = blockIdx.x, h = blockIdx.y, b = blockIdx.z;
    int kh = h >> 2;
    int tid = threadIdx.x;
    int w = tid >> 5, lane = tid & 31, gp = lane >> 2, t4 = lane & 3;

#pragma unroll
    for (int i = 0; i < 8; i++) {
        int id = tid + i*256;
        int q = id >> 4, d4 = id & 15;
        float4 v = *(const float4*)(Q + ((size_t)(b*S_ + qt*128 + q))*(H_*HD_) + h*HD_ + d4*4);
        float vv[4] = {v.x*0.125f, v.y*0.125f, v.z*0.125f, v.w*0.125f};
        float4 hi, lo; float* hp = &hi.x; float* lp = &lo.x;
#pragma unroll
        for (int j = 0; j < 4; j++) {
            unsigned hb = f2tf(vv[j]);
            hp[j] = __uint_as_float(hb);
            lp[j] = __uint_as_float(f2tf(vv[j] - __uint_as_float(hb)));
        }
        *(float4*)(Qh + q*68 + d4*4) = hi;
        *(float4*)(Ql + q*68 + d4*4) = lo;
    }

    float m0 = NEG_BIG, m1 = NEG_BIG, l0 = 0.f, l1 = 0.f;
    float o[8][4];
#pragma unroll
    for (int nt = 0; nt < 8; nt++)
#pragma unroll
        for (int j = 0; j < 4; j++) o[nt][j] = 0.f;
    int nkt = 2*(qt + 1);
    int lr0 = w*16 + gp, lr1 = lr0 + 8;

    for (int kt = 0; kt < nkt; kt++) {
        __syncthreads();
#pragma unroll
        for (int i = 0; i < 4; i++) {
            int id = tid + i*256;
            int k = id >> 4, d4 = id & 15;
            size_t gb = ((size_t)(b*S_ + kt*64 + k))*(KH_*HD_) + kh*HD_ + d4*4;
            float4 kv = *(const float4*)(Kb + gb);
            float4 vv4 = *(const float4*)(Vb + gb);
            float kk[4] = {kv.x, kv.y, kv.z, kv.w};
            float vvv[4] = {vv4.x, vv4.y, vv4.z, vv4.w};
            float4 khi, klo, vhi, vlo;
            float* khp = &khi.x; float* klp = &klo.x;
            float* vhp = &vhi.x; float* vlp = &vlo.x;
#pragma unroll
            for (int j = 0; j < 4; j++) {
                unsigned hb = f2tf(kk[j]);
                khp[j] = __uint_as_float(hb);
                klp[j] = __uint_as_float(f2tf(kk[j] - __uint_as_float(hb)));
                unsigned vb2 = f2tf(vvv[j]);
                vhp[j] = __uint_as_float(vb2);
                vlp[j] = __uint_as_float(f2tf(vvv[j] - __uint_as_float(vb2)));
            }
            *(float4*)(Kh + k*68 + d4*4) = khi;
            *(float4*)(Kl + k*68 + d4*4) = klo;
            *(float4*)(Vh + k*72 + d4*4) = vhi;
            *(float4*)(Vl + k*72 + d4*4) = vlo;
        }
        __syncthreads();

        float s[8][4];
#pragma unroll
        for (int nt = 0; nt < 8; nt++)
#pragma unroll
            for (int j = 0; j < 4; j++) s[nt][j] = 0.f;
#pragma unroll
        for (int kb = 0; kb < 8; kb++) {
            int arow = lr0*68 + kb*8 + t4;
            unsigned ah[4], al2[4];
            ah[0] = __float_as_uint(Qh[arow]);
            ah[1] = __float_as_uint(Qh[arow + 8*68]);
            ah[2] = __float_as_uint(Qh[arow + 4]);
            ah[3] = __float_as_uint(Qh[arow + 8*68 + 4]);
            al2[0] = __float_as_uint(Ql[arow]);
            al2[1] = __float_as_uint(Ql[arow + 8*68]);
            al2[2] = __float_as_uint(Ql[arow + 4]);
            al2[3] = __float_as_uint(Ql[arow + 8*68 + 4]);
#pragma unroll
            for (int nt = 0; nt < 8; nt++) {
                int baddr = (nt*8 + gp)*68 + kb*8 + t4;
                unsigned bh0 = __float_as_uint(Kh[baddr]);
                unsigned bh1 = __float_as_uint(Kh[baddr + 4]);
                unsigned bl0 = __float_as_uint(Kl[baddr]);
                unsigned bl1 = __float_as_uint(Kl[baddr + 4]);
                mma_tf32(s[nt], ah, bh0, bh1);
                mma_tf32(s[nt], ah, bl0, bl1);
                mma_tf32(s[nt], al2, bh0, bh1);
            }
        }

        int qrow0 = qt*128 + lr0;
        int qrow1 = qt*128 + lr1;
        int colb = kt*64;
#pragma unroll
        for (int nt = 0; nt < 8; nt++) {
            int c0 = colb + nt*8 + t4*2;
            if (c0     > qrow0) s[nt][0] = NEG_BIG;
            if (c0 + 1 > qrow0) s[nt][1] = NEG_BIG;
            if (c0     > qrow1) s[nt][2] = NEG_BIG;
            if (c0 + 1 > qrow1) s[nt][3] = NEG_BIG;
        }
        float mx0 = NEG_BIG, mx1 = NEG_BIG;
#pragma unroll
        for (int nt = 0; nt < 8; nt++) {
            mx0 = fmaxf(mx0, fmaxf(s[nt][0], s[nt][1]));
            mx1 = fmaxf(mx1, fmaxf(s[nt][2], s[nt][3]));
        }
        mx0 = fmaxf(mx0, __shfl_xor_sync(0xffffffffu, mx0, 1));
        mx0 = fmaxf(mx0, __shfl_xor_sync(0xffffffffu, mx0, 2));
        mx1 = fmaxf(mx1, __shfl_xor_sync(0xffffffffu, mx1, 1));
        mx1 = fmaxf(mx1, __shfl_xor_sync(0xffffffffu, mx1, 2));
        float mn0 = fmaxf(m0, mx0), mn1 = fmaxf(m1, mx1);
        float al0 = __expf(m0 - mn0), al1 = __expf(m1 - mn1);
        float ls0 = 0.f, ls1 = 0.f;
#pragma unroll
        for (int nt = 0; nt < 8; nt++) {
            float e0 = __expf(s[nt][0] - mn0); s[nt][0] = e0; ls0 += e0;
            float e1 = __expf(s[nt][1] - mn0); s[nt][1] = e1; ls0 += e1;
            float e2 = __expf(s[nt][2] - mn1); s[nt][2] = e2; ls1 += e2;
            float e3 = __expf(s[nt][3] - mn1); s[nt][3] = e3; ls1 += e3;
        }
        ls0 += __shfl_xor_sync(0xffffffffu, ls0, 1);
        ls0 += __shfl_xor_sync(0xffffffffu, ls0, 2);
        ls1 += __shfl_xor_sync(0xffffffffu, ls1, 1);
        ls1 += __shfl_xor_sync(0xffffffffu, ls1, 2);
        l0 = l0*al0 + ls0; m0 = mn0;
        l1 = l1*al1 + ls1; m1 = mn1;

#pragma unroll
        for (int nt = 0; nt < 8; nt++) {
            float p0 = s[nt][0], p1 = s[nt][1], p2 = s[nt][2], p3 = s[nt][3];
            unsigned h0 = f2tf(p0), h1 = f2tf(p1), h2 = f2tf(p2), h3 = f2tf(p3);
            int c = nt*8 + t4*2;
            *(float2*)(Ph + lr0*68 + c) = make_float2(__uint_as_float(h0), __uint_as_float(h1));
            *(float2*)(Ph + lr1*68 + c) = make_float2(__uint_as_float(h2), __uint_as_float(h3));
            *(float2*)(Pl + lr0*68 + c) = make_float2(
                __uint_as_float(f2tf(p0 - __uint_as_float(h0))),
                __uint_as_float(f2tf(p1 - __uint_as_float(h1))));
            *(float2*)(Pl + lr1*68 + c) = make_float2(
                __uint_as_float(f2tf(p2 - __uint_as_float(h2))),
                __uint_as_float(f2tf(p3 - __uint_as_float(h3))));
            o[nt][0] *= al0; o[nt][1] *= al0;
            o[nt][2] *= al1; o[nt][3] *= al1;
        }
        __syncthreads();

#pragma unroll
        for (int kb = 0; kb < 8; kb++) {
            int arow = lr0*68 + kb*8 + t4;
            unsigned ah[4], al2[4];
            ah[0] = __float_as_uint(Ph[arow]);
            ah[1] = __float_as_uint(Ph[arow + 8*68]);
            ah[2] = __float_as_uint(Ph[arow + 4]);
            ah[3] = __float_as_uint(Ph[arow + 8*68 + 4]);
            al2[0] = __float_as_uint(Pl[arow]);
            al2[1] = __float_as_uint(Pl[arow + 8*68]);
            al2[2] = __float_as_uint(Pl[arow + 4]);
            al2[3] = __float_as_uint(Pl[arow + 8*68 + 4]);
            int krow = (kb*8 + t4)*72;
#pragma unroll
            for (int nt = 0; nt < 8; nt++) {
                int bcol = nt*8 + gp;
                unsigned bh0 = __float_as_uint(Vh[krow + bcol]);
                unsigned bh1 = __float_as_uint(Vh[krow + 4*72 + bcol]);
                unsigned bl0 = __float_as_uint(Vl[krow + bcol]);
                unsigned bl1 = __float_as_uint(Vl[krow + 4*72 + bcol]);
                mma_tf32(o[nt], ah, bh0, bh1);
                mma_tf32(o[nt], ah, bl0, bl1);
                mma_tf32(o[nt], al2, bh0, bh1);
            }
        }
    }
    // epilogue: attn*sigmoid(gate) written in place to G
    float inv0 = 1.f / l0, inv1 = 1.f / l1;
    size_t ob0 = ((size_t)(b*S_ + qt*128 + lr0))*(H_*HD_) + h*HD_;
    size_t ob1 = ((size_t)(b*S_ + qt*128 + lr1))*(H_*HD_) + h*HD_;
#pragma unroll
    for (int nt = 0; nt < 8; nt++) {
        int c = nt*8 + t4*2;
        float2 gv0 = *(float2*)(G + ob0 + c);
        float2 gv1 = *(float2*)(G + ob1 + c);
        float2 r0, r1;
        r0.x = o[nt][0]*inv0 / (1.f + __expf(-gv0.x));
        r0.y = o[nt][1]*inv0 / (1.f + __expf(-gv0.y));
        r1.x = o[nt][2]*inv1 / (1.f + __expf(-gv1.x));
        r1.y = o[nt][3]*inv1 / (1.f + __expf(-gv1.y));
        *(float2*)(G + ob0 + c) = r0;
        *(float2*)(G + ob1 + c) = r1;
    }
}

// ======= router + moe bookkeeping =======
__global__ void router_kernel(const float* __restrict__ rw) {
    int t = blockIdx.x;
    const float* x = g_xn2 + (size_t)t * D_;
    float le[8] = {0,0,0,0,0,0,0,0};
    for (int d = threadIdx.x; d < D_; d += 256) {
        float xv = x[d];
        const float4* r4 = (const float4*)(rw + (size_t)d * 8);
        float4 aa = r4[0], bb = r4[1];
        le[0] += xv*aa.x; le[1] += xv*aa.y; le[2] += xv*aa.z; le[3] += xv*aa.w;
        le[4] += xv*bb.x; le[5] += xv*bb.y; le[6] += xv*bb.z; le[7] += xv*bb.w;
    }
#pragma unroll
    for (int e = 0; e < 8; e++)
        for (int o = 16; o > 0; o >>= 1)
            le[e] += __shfl_xor_sync(0xffffffffu, le[e], o);
    __shared__ float smr[8][8];
    if ((threadIdx.x & 31) == 0)
#pragma unroll
        for (int e = 0; e < 8; e++) smr[threadIdx.x >> 5][e] = le[e];
    __syncthreads();
    if (threadIdx.x == 0) {
        float lg[8];
#pragma unroll
        for (int e = 0; e < 8; e++) {
            float s = 0.f;
            for (int w2 = 0; w2 < 8; w2++) s += smr[w2][e];
            lg[e] = s;
        }
        float mx = lg[0];
        for (int e = 1; e < 8; e++) mx = fmaxf(mx, lg[e]);
        float p[8], s = 0.f;
        for (int e = 0; e < 8; e++) { p[e] = expf(lg[e] - mx); s += p[e]; }
        float invs = 1.f / s;
        for (int e = 0; e < 8; e++) { p[e] *= invs; atomicAdd(&g_probsum[e], p[e]); }
        int i0 = 0;
        for (int e = 1; e < 8; e++) if (p[e] > p[i0]) i0 = e;
        int i1 = (i0 == 0) ? 1 : 0;
        for (int e = 0; e < 8; e++) if (e != i0 && p[e] > p[i1]) i1 = e;
        float tv0 = p[i0], tv1 = p[i1], s2 = tv0 + tv1;
        g_topi[t*2] = i0; g_topi[t*2+1] = i1;
        g_topv[t*2] = tv0/s2; g_topv[t*2+1] = tv1/s2;
        atomicAdd(&g_counts[i0], 1);
        atomicAdd(&g_counts[i1], 1);
    }
}
__global__ void zero_kernel() {
    int t = threadIdx.x;
    if (t < E_) { g_counts[t] = 0; g_cursor[t] = 0; g_probsum[t] = 0.f; }
}
__global__ void offsets_aux_kernel(float* __restrict__ aux_out) {
    if (threadIdx.x == 0) {
        int o = 0;
        for (int e = 0; e < E_; e++) { g_off[e] = o; o += g_counts[e]; }
        g_off[E_] = o;
        float aux = 0.f;
        for (int e = 0; e < E_; e++)
            aux += ((float)g_counts[e] / (NTOK*2.0f)) * (g_probsum[e] / (float)NTOK);
        aux_out[0] = 0.01f * (float)E_ * aux;
    }
}
__global__ void scatter_kernel() {
    int t = blockIdx.x * 256 + threadIdx.x;
    if (t >= NTOK) return;
#pragma unroll
    for (int k2 = 0; k2 < 2; k2++) {
        int e = g_topi[t*2+k2];
        int pos = g_off[e] + atomicAdd(&g_cursor[e], 1);
        g_permTok[pos] = t;
        g_permW[pos] = g_topv[t*2+k2];
        g_tokSlot[t*2+k2] = pos;
    }
}
__global__ void finaladd_kernel(float* __restrict__ out) {
    size_t i = (size_t)blockIdx.x * 256 + threadIdx.x;
    int t = (int)(i >> 10);
    int d = (int)(i & 1023);
    int s0 = g_tokSlot[t*2], s1 = g_tokSlot[t*2+1];
    out[i] = g_x1[i] + g_tmp[(size_t)s0*D_ + d] + g_tmp[(size_t)s1*D_ + d];
}

// ======= host launcher =======
extern "C" void kernel_launch(void* const* d_in, const int* in_sizes, int n_in,
                              void* d_out, int out_size) {
    const float* x        = (const float*)d_in[0];
    const float* attn_nw  = (const float*)d_in[1];
    const float* ffn_nw   = (const float*)d_in[2];
    const float* q_nw     = (const float*)d_in[3];
    const float* k_nw     = (const float*)d_in[4];
    const float* wq       = (const float*)d_in[5];
    const float* wk       = (const float*)d_in[6];
    const float* wv       = (const float*)d_in[7];
    const float* wo       = (const float*)d_in[8];
    const float* wg       = (const float*)d_in[9];
    const float* router_w = (const float*)d_in[10];
    const float* w1       = (const float*)d_in[11];
    const float* w3       = (const float*)d_in[12];
    const float* w2       = (const float*)d_in[13];
    float* out = (float*)d_out;

    float *p_xn, *p_q, *p_k, *p_v, *p_gate, *p_x1, *p_xn2;
    cudaGetSymbolAddress((void**)&p_xn, g_xn);
    cudaGetSymbolAddress((void**)&p_q, g_q);
    cudaGetSymbolAddress((void**)&p_k, g_k);
    cudaGetSymbolAddress((void**)&p_v, g_v);
    cudaGetSymbolAddress((void**)&p_gate, g_gate);
    cudaGetSymbolAddress((void**)&p_x1, g_x1);
    cudaGetSymbolAddress((void**)&p_xn2, g_xn2);

    cudaFuncSetAttribute(proj_gemm, cudaFuncAttributeMaxDynamicSharedMemorySize, SMEM_GEMM_S);
    cudaFuncSetAttribute(gemm_plain<1,true>, cudaFuncAttributeMaxDynamicSharedMemorySize, SMEM_GEMM_S);
    cudaFuncSetAttribute(moe13_fused, cudaFuncAttributeMaxDynamicSharedMemorySize, SMEM_GEMM);
    cudaFuncSetAttribute(moe2_gemm, cudaFuncAttributeMaxDynamicSharedMemorySize, SMEM_GEMM);
    cudaFuncSetAttribute(attn_tc2, cudaFuncAttributeMaxDynamicSharedMemorySize, SMEM_ATTN3);

    rmsnorm_kernel<<<NTOK, 256>>>(x, attn_nw, p_xn, 1e-6f);
    proj_gemm<<<dim3(20,32), 256, SMEM_GEMM_S>>>(wq, wk, wv, wg);
    qkrope_kernel<<<(NTOK*H_*32)/256, 256>>>(p_q, q_nw, H_);
    qkrope_kernel<<<(NTOK*KH_*32)/256, 256>>>(p_k, k_nw, KH_);
    attn_tc2<<<dim3(S_/128, H_, B_), 256, SMEM_ATTN3>>>(p_q, p_k, p_v, p_gate);
    gemm_plain<1,true><<<dim3(8,32), 256, SMEM_GEMM_S>>>(p_gate, wo, p_x1, x, 1024, 1024, NTOK);
    rmsnorm_kernel<<<NTOK, 256>>>(p_x1, ffn_nw, p_xn2, 1e-6f);
    zero_kernel<<<1, 32>>>();
    router_kernel<<<NTOK, 256>>>(router_w);
    offsets_aux_kernel<<<1, 32>>>(out + (size_t)NTOK*D_);
    scatter_kernel<<<NTOK/256, 256>>>();
    moe13_fused<<<dim3(FF_/64, 32, 8), 256, SMEM_GEMM>>>(w1, w3);
    moe2_gemm<<<dim3(D_/128, 32, 8), 256, SMEM_GEMM>>>(w2);
    finaladd_kernel<<<(NTOK*1024)/256, 256>>>(out);
}

// round 9
// speedup vs baseline: 1.0601x; 1.0601x over previous
#include <cuda_runtime.h>
#include <math.h>
#include <stdint.h>

#define B_ 2
#define S_ 2048
#define D_ 1024
#define H_ 16
#define KH_ 4
#define HD_ 64
#define E_ 8
#define FF_ 2048
#define NTOK (B_*S_)
#define NSLOT (NTOK*2)
#define NEG_BIG -3.0e38f

#define BM 128
#define BN 128
#define LDA 36
#define LDB 136
#define PLANE (BM*LDA + 32*LDB)
#define SMEM_GEMM   (2*PLANE*4)
#define SMEM_GEMM_S (4*PLANE*4)
// attn smem: Qh,Ql[128][68], Kh,Kl[64][68], Vh,Vl[64][72], Ph,Pl[128][68]
#define SMEM_ATTN3 ((2*128*68 + 2*64*68 + 2*64*72 + 2*128*68)*4)

__device__ float g_xn  [NTOK*D_];
__device__ float g_q   [NTOK*H_*HD_];
__device__ float g_k   [NTOK*KH_*HD_];
__device__ float g_v   [NTOK*KH_*HD_];
__device__ float g_gate[NTOK*H_*HD_];
__device__ float g_x1  [NTOK*D_];
__device__ float g_xn2 [NTOK*D_];
__device__ float g_h   [(size_t)NSLOT*FF_];
__device__ float g_h3  [(size_t)NSLOT*FF_];
__device__ float g_tmp [(size_t)NSLOT*D_];
__device__ int   g_topi[NTOK*2];
__device__ float g_topv[NTOK*2];
__device__ int   g_permTok[NSLOT];
__device__ float g_permW  [NSLOT];
__device__ int   g_tokSlot[NTOK*2];
__device__ int   g_counts[E_];
__device__ int   g_off   [E_+1];
__device__ int   g_cursor[E_];
__device__ float g_probsum[E_];

__device__ __forceinline__ unsigned f2tf(float v) {
    unsigned r; asm("cvt.rna.tf32.f32 %0, %1;" : "=r"(r) : "f"(v)); return r;
}
__device__ __forceinline__ void mma_tf32(float* d, const unsigned* a, unsigned b0, unsigned b1) {
    asm volatile("mma.sync.aligned.m16n8k8.row.col.f32.tf32.tf32.f32 "
        "{%0,%1,%2,%3}, {%4,%5,%6,%7}, {%8,%9}, {%0,%1,%2,%3};"
        : "+f"(d[0]), "+f"(d[1]), "+f"(d[2]), "+f"(d[3])
        : "r"(a[0]), "r"(a[1]), "r"(a[2]), "r"(a[3]), "r"(b0), "r"(b1));
}

// ======= tf32 MMA GEMM 128x128x32, double-buffered. EPI: 0 plain, 1 +X, 3 X[row]* =======
template<int EPI, bool SPLIT>
__device__ __forceinline__ void gemm_core(
    const float* __restrict__ A, const float* __restrict__ B,
    float* __restrict__ C, const float* __restrict__ X,
    int N, int K, int ldc, int rowstart, int rowend,
    const int* __restrict__ rowmap, int bx, int by)
{
    extern __shared__ float sm[];
    const int SS = PLANE * (SPLIT ? 2 : 1);
    int tid = threadIdx.x;
    int rowbase = rowstart + by*BM;
    if (rowbase >= rowend) return;
    int nbase = bx*BN;
    int k4 = tid & 7, n4 = tid & 31;
    const float* aP[4]; bool av[4];
#pragma unroll
    for (int i = 0; i < 4; i++) {
        int grow = rowbase + (tid >> 3) + 32*i;
        av[i] = grow < rowend;
        int ar = av[i] ? (rowmap ? rowmap[grow] : grow)
                       : (rowmap ? rowmap[rowstart] : rowstart);
        aP[i] = A + (size_t)ar*K + k4*4;
    }
    const float* bP = B + (size_t)(tid>>5)*N + nbase + n4*4;
    int lane = tid & 31, gp = lane >> 2, t4 = lane & 3;
    int w = tid >> 5, mb = (w & 3)*32, nb = (w >> 2)*64;

    float acc[2][8][4];
#pragma unroll
    for (int a = 0; a < 2; a++)
#pragma unroll
        for (int b = 0; b < 8; b++)
#pragma unroll
            for (int c = 0; c < 4; c++) acc[a][b][c] = 0.f;

    float4 va[4], vb[4];
#pragma unroll
    for (int i = 0; i < 4; i++) {
        va[i] = av[i] ? *(const float4*)aP[i] : make_float4(0,0,0,0);
        vb[i] = *(const float4*)(bP + (size_t)(8*i)*N);
    }
    int nkt = K >> 5;

    auto stage = [&](float* base) {
        float* Ah = base; float* Bh = base + BM*LDA;
        float* Al = Bh + 32*LDB; float* Bl = Al + BM*LDA;
#pragma unroll
        for (int i = 0; i < 4; i++) {
            int m = (tid >> 3) + 32*i;
            float vv[4] = {va[i].x, va[i].y, va[i].z, va[i].w};
            float4 hi, lo; float* hp = &hi.x; float* lp = &lo.x;
#pragma unroll
            for (int j = 0; j < 4; j++) {
                unsigned h2 = f2tf(vv[j]);
                hp[j] = __uint_as_float(h2);
                if (SPLIT) lp[j] = __uint_as_float(f2tf(vv[j] - __uint_as_float(h2)));
            }
            *(float4*)(Ah + m*LDA + k4*4) = hi;
            if (SPLIT) *(float4*)(Al + m*LDA + k4*4) = lo;
            int kr = (tid >> 5) + 8*i;
            float bv[4] = {vb[i].x, vb[i].y, vb[i].z, vb[i].w};
#pragma unroll
            for (int j = 0; j < 4; j++) {
                unsigned h2 = f2tf(bv[j]);
                hp[j] = __uint_as_float(h2);
                if (SPLIT) lp[j] = __uint_as_float(f2tf(bv[j] - __uint_as_float(h2)));
            }
            *(float4*)(Bh + kr*LDB + n4*4) = hi;
            if (SPLIT) *(float4*)(Bl + kr*LDB + n4*4) = lo;
        }
    };
    auto compute = [&](float* base) {
        float* Ah = base; float* Bh = base + BM*LDA;
        float* Al = Bh + 32*LDB; float* Bl = Al + BM*LDA;
#pragma unroll
        for (int ks = 0; ks < 4; ks++) {
            int kf = ks*8 + t4;
            unsigned a[2][4], al[2][4];
#pragma unroll
            for (int mt = 0; mt < 2; mt++) {
                int r = mb + mt*16 + gp;
                a[mt][0] = __float_as_uint(Ah[r*LDA + kf]);
                a[mt][1] = __float_as_uint(Ah[(r+8)*LDA + kf]);
                a[mt][2] = __float_as_uint(Ah[r*LDA + kf + 4]);
                a[mt][3] = __float_as_uint(Ah[(r+8)*LDA + kf + 4]);
                if (SPLIT) {
                    al[mt][0] = __float_as_uint(Al[r*LDA + kf]);
                    al[mt][1] = __float_as_uint(Al[(r+8)*LDA + kf]);
                    al[mt][2] = __float_as_uint(Al[r*LDA + kf + 4]);
                    al[mt][3] = __float_as_uint(Al[(r+8)*LDA + kf + 4]);
                }
            }
#pragma unroll
            for (int nt = 0; nt < 8; nt++) {
                int c = nb + nt*8 + gp;
                unsigned b0 = __float_as_uint(Bh[kf*LDB + c]);
                unsigned b1 = __float_as_uint(Bh[(kf+4)*LDB + c]);
#pragma unroll
                for (int mt = 0; mt < 2; mt++) mma_tf32(acc[mt][nt], a[mt], b0, b1);
                if (SPLIT) {
                    unsigned c0 = __float_as_uint(Bl[kf*LDB + c]);
                    unsigned c1 = __float_as_uint(Bl[(kf+4)*LDB + c]);
#pragma unroll
                    for (int mt = 0; mt < 2; mt++) {
                        mma_tf32(acc[mt][nt], a[mt], c0, c1);
                        mma_tf32(acc[mt][nt], al[mt], b0, b1);
                    }
                }
            }
        }
    };

    stage(sm);
    __syncthreads();
    for (int kt = 0; kt < nkt; kt++) {
        if (kt + 1 < nkt) {
#pragma unroll
            for (int i = 0; i < 4; i++) {
                va[i] = av[i] ? *(const float4*)(aP[i] + (kt+1)*32) : make_float4(0,0,0,0);
                vb[i] = *(const float4*)(bP + (size_t)((kt+1)*32 + 8*i)*N);
            }
        }
        compute(sm + (kt & 1)*SS);
        if (kt + 1 < nkt) stage(sm + ((kt+1) & 1)*SS);
        __syncthreads();
    }
#pragma unroll
    for (int mt = 0; mt < 2; mt++) {
        int r0 = rowbase + mb + mt*16 + gp;
        int r1 = r0 + 8;
        float s0 = 0.f, s1 = 0.f;
        if (EPI == 3) {
            s0 = (r0 < rowend) ? X[r0] : 0.f;
            s1 = (r1 < rowend) ? X[r1] : 0.f;
        }
#pragma unroll
        for (int nt = 0; nt < 8; nt++) {
            int col = nbase + nb + nt*8 + t4*2;
            if (r0 < rowend) {
                float2 v = make_float2(acc[mt][nt][0], acc[mt][nt][1]);
                if (EPI == 1) { float2 xr = *(const float2*)(X + (size_t)r0*ldc + col); v.x += xr.x; v.y += xr.y; }
                if (EPI == 3) { v.x *= s0; v.y *= s0; }
                *(float2*)(C + (size_t)r0*ldc + col) = v;
            }
            if (r1 < rowend) {
                float2 v = make_float2(acc[mt][nt][2], acc[mt][nt][3]);
                if (EPI == 1) { float2 xr = *(const float2*)(X + (size_t)r1*ldc + col); v.x += xr.x; v.y += xr.y; }
                if (EPI == 3) { v.x *= s1; v.y *= s1; }
                *(float2*)(C + (size_t)r1*ldc + col) = v;
            }
        }
    }
}

template<int EPI, bool SPLIT>
__global__ void __launch_bounds__(256) gemm_plain(
    const float* __restrict__ A, const float* __restrict__ B,
    float* __restrict__ C, const float* __restrict__ X, int N, int K, int M)
{
    gemm_core<EPI,SPLIT>(A, B, C, X, N, K, N, 0, M, nullptr, blockIdx.x, blockIdx.y);
}

__global__ void __launch_bounds__(256) proj_gemm(
    const float* __restrict__ wq, const float* __restrict__ wk,
    const float* __restrict__ wv, const float* __restrict__ wg)
{
    int bx = blockIdx.x;
    const float* Bp; float* C; int N; int lbx;
    if (bx < 8)       { Bp = wq; C = g_q;    N = 1024; lbx = bx; }
    else if (bx < 10) { Bp = wk; C = g_k;    N = 256;  lbx = bx - 8; }
    else if (bx < 12) { Bp = wv; C = g_v;    N = 256;  lbx = bx - 10; }
    else              { Bp = wg; C = g_gate; N = 1024; lbx = bx - 12; }
    gemm_core<0,true>(g_xn, Bp, C, nullptr, N, 1024, N, 0, NTOK, nullptr, lbx, blockIdx.y);
}

__global__ void __launch_bounds__(256) moe13_gemm(
    const float* __restrict__ w1, const float* __restrict__ w3)
{
    int z = blockIdx.z, e = z >> 1;
    const float* B = ((z & 1) ? w3 : w1) + (size_t)e*D_*FF_;
    float* C = (z & 1) ? g_h3 : g_h;
    gemm_core<0,false>(g_xn2, B, C, nullptr, FF_, D_, FF_,
                       g_off[e], g_off[e+1], g_permTok, blockIdx.x, blockIdx.y);
}
__global__ void __launch_bounds__(256) moe2_gemm(const float* __restrict__ w2)
{
    int e = blockIdx.z;
    gemm_core<3,false>(g_h, w2 + (size_t)e*FF_*D_, g_tmp, g_permW, D_, FF_, D_,
                       g_off[e], g_off[e+1], nullptr, blockIdx.x, blockIdx.y);
}

// ======= rmsnorm =======
__global__ void rmsnorm_kernel(const float* __restrict__ x, const float* __restrict__ w,
                               float* __restrict__ out, float eps) {
    int t = blockIdx.x;
    const float4* xr = (const float4*)(x + (size_t)t * D_);
    float4 v = xr[threadIdx.x];
    float ss = v.x*v.x + v.y*v.y + v.z*v.z + v.w*v.w;
    __shared__ float smr[8];
    for (int o = 16; o > 0; o >>= 1) ss += __shfl_xor_sync(0xffffffffu, ss, o);
    if ((threadIdx.x & 31) == 0) smr[threadIdx.x >> 5] = ss;
    __syncthreads();
    if (threadIdx.x < 8) {
        float s2 = smr[threadIdx.x];
        for (int o = 4; o > 0; o >>= 1) s2 += __shfl_xor_sync(0xffu, s2, o);
        if (threadIdx.x == 0) smr[0] = s2;
    }
    __syncthreads();
    float sc = rsqrtf(smr[0] * (1.0f / D_) + eps);
    float4 wv = ((const float4*)w)[threadIdx.x];
    ((float4*)(out + (size_t)t * D_))[threadIdx.x] =
        make_float4(v.x*sc*wv.x, v.y*sc*wv.y, v.z*sc*wv.z, v.w*sc*wv.w);
}

// ======= q/k rmsnorm + rope =======
__global__ void qkrope_kernel(float* buf, const float* __restrict__ w, int nheads) {
    int wid = (blockIdx.x * blockDim.x + threadIdx.x) >> 5;
    int lane = threadIdx.x & 31;
    int t = wid / nheads, h = wid - t * nheads;
    int pos = t & (S_ - 1);
    size_t base = (size_t)t * nheads * HD_ + h * HD_;
    float v0 = buf[base + 2*lane], v1 = buf[base + 2*lane + 1];
    float ss = v0*v0 + v1*v1;
    for (int o = 16; o > 0; o >>= 1) ss += __shfl_xor_sync(0xffffffffu, ss, o);
    float sc = rsqrtf(ss * (1.0f / HD_) + 1e-5f);
    float a  = v0 * sc * w[2*lane];
    float b2 = v1 * sc * w[2*lane + 1];
    float inv = expf(-(float)lane * (2.0f / HD_) * 9.210340371976184f);
    float ang = (float)pos * inv;
    float cs = cosf(ang), sn = sinf(ang);
    buf[base + 2*lane]     = a*cs - b2*sn;
    buf[base + 2*lane + 1] = a*sn + b2*cs;
}

// ======= attention: split-tf32 MMA QK^T + PV, register m/l, fused gate =======
__global__ void __launch_bounds__(256) attn_tc2(
    const float* __restrict__ Q, const float* __restrict__ Kb,
    const float* __restrict__ Vb, float* __restrict__ G)
{
    extern __shared__ float sma[];
    float* Qh = sma;                  // [128][68]
    float* Ql = Qh + 128*68;
    float* Kh = Ql + 128*68;          // [64][68]
    float* Kl = Kh + 64*68;
    float* Vh = Kl + 64*68;           // [64][72]
    float* Vl = Vh + 64*72;
    float* Ph = Vl + 64*72;           // [128][68]
    float* Pl = Ph + 128*68;
    int qt = (int)(gridDim.x - 1 - blockIdx.x);   // heavy tiles first
    int h = blockIdx.y, b = blockIdx.z;
    int kh = h >> 2;
    int tid = threadIdx.x;
    int w = tid >> 5, lane = tid & 31, gp = lane >> 2, t4 = lane & 3;

#pragma unroll
    for (int i = 0; i < 8; i++) {
        int id = tid + i*256;
        int q = id >> 4, d4 = id & 15;
        float4 v = *(const float4*)(Q + ((size_t)(b*S_ + qt*128 + q))*(H_*HD_) + h*HD_ + d4*4);
        float vv[4] = {v.x*0.125f, v.y*0.125f, v.z*0.125f, v.w*0.125f};
        float4 hi, lo; float* hp = &hi.x; float* lp = &lo.x;
#pragma unroll
        for (int j = 0; j < 4; j++) {
            unsigned hb = f2tf(vv[j]);
            hp[j] = __uint_as_float(hb);
            lp[j] = __uint_as_float(f2tf(vv[j] - __uint_as_float(hb)));
        }
        *(float4*)(Qh + q*68 + d4*4) = hi;
        *(float4*)(Ql + q*68 + d4*4) = lo;
    }

    float m0 = NEG_BIG, m1 = NEG_BIG, l0 = 0.f, l1 = 0.f;
    float o[8][4];
#pragma unroll
    for (int nt = 0; nt < 8; nt++)
#pragma unroll
        for (int j = 0; j < 4; j++) o[nt][j] = 0.f;
    int nkt = 2*(qt + 1);
    int lr0 = w*16 + gp, lr1 = lr0 + 8;

    for (int kt = 0; kt < nkt; kt++) {
        __syncthreads();
#pragma unroll
        for (int i = 0; i < 4; i++) {
            int id = tid + i*256;
            int k = id >> 4, d4 = id & 15;
            size_t gb = ((size_t)(b*S_ + kt*64 + k))*(KH_*HD_) + kh*HD_ + d4*4;
            float4 kv = *(const float4*)(Kb + gb);
            float4 vv4 = *(const float4*)(Vb + gb);
            float kk[4] = {kv.x, kv.y, kv.z, kv.w};
            float vvv[4] = {vv4.x, vv4.y, vv4.z, vv4.w};
            float4 khi, klo, vhi, vlo;
            float* khp = &khi.x; float* klp = &klo.x;
            float* vhp = &vhi.x; float* vlp = &vlo.x;
#pragma unroll
            for (int j = 0; j < 4; j++) {
                unsigned hb = f2tf(kk[j]);
                khp[j] = __uint_as_float(hb);
                klp[j] = __uint_as_float(f2tf(kk[j] - __uint_as_float(hb)));
                unsigned vb2 = f2tf(vvv[j]);
                vhp[j] = __uint_as_float(vb2);
                vlp[j] = __uint_as_float(f2tf(vvv[j] - __uint_as_float(vb2)));
            }
            *(float4*)(Kh + k*68 + d4*4) = khi;
            *(float4*)(Kl + k*68 + d4*4) = klo;
            *(float4*)(Vh + k*72 + d4*4) = vhi;
            *(float4*)(Vl + k*72 + d4*4) = vlo;
        }
        __syncthreads();

        float s[8][4];
#pragma unroll
        for (int nt = 0; nt < 8; nt++)
#pragma unroll
            for (int j = 0; j < 4; j++) s[nt][j] = 0.f;
#pragma unroll
        for (int kb = 0; kb < 8; kb++) {
            int arow = lr0*68 + kb*8 + t4;
            unsigned ah[4], al2[4];
            ah[0] = __float_as_uint(Qh[arow]);
            ah[1] = __float_as_uint(Qh[arow + 8*68]);
            ah[2] = __float_as_uint(Qh[arow + 4]);
            ah[3] = __float_as_uint(Qh[arow + 8*68 + 4]);
            al2[0] = __float_as_uint(Ql[arow]);
            al2[1] = __float_as_uint(Ql[arow + 8*68]);
            al2[2] = __float_as_uint(Ql[arow + 4]);
            al2[3] = __float_as_uint(Ql[arow + 8*68 + 4]);
#pragma unroll
            for (int nt = 0; nt < 8; nt++) {
                int baddr = (nt*8 + gp)*68 + kb*8 + t4;
                unsigned bh0 = __float_as_uint(Kh[baddr]);
                unsigned bh1 = __float_as_uint(Kh[baddr + 4]);
                unsigned bl0 = __float_as_uint(Kl[baddr]);
                unsigned bl1 = __float_as_uint(Kl[baddr + 4]);
                mma_tf32(s[nt], ah, bh0, bh1);
                mma_tf32(s[nt], ah, bl0, bl1);
                mma_tf32(s[nt], al2, bh0, bh1);
            }
        }

        int qrow0 = qt*128 + lr0;
        int qrow1 = qt*128 + lr1;
        int colb = kt*64;
#pragma unroll
        for (int nt = 0; nt < 8; nt++) {
            int c0 = colb + nt*8 + t4*2;
            if (c0     > qrow0) s[nt][0] = NEG_BIG;
            if (c0 + 1 > qrow0) s[nt][1] = NEG_BIG;
            if (c0     > qrow1) s[nt][2] = NEG_BIG;
            if (c0 + 1 > qrow1) s[nt][3] = NEG_BIG;
        }
        float mx0 = NEG_BIG, mx1 = NEG_BIG;
#pragma unroll
        for (int nt = 0; nt < 8; nt++) {
            mx0 = fmaxf(mx0, fmaxf(s[nt][0], s[nt][1]));
            mx1 = fmaxf(mx1, fmaxf(s[nt][2], s[nt][3]));
        }
        mx0 = fmaxf(mx0, __shfl_xor_sync(0xffffffffu, mx0, 1));
        mx0 = fmaxf(mx0, __shfl_xor_sync(0xffffffffu, mx0, 2));
        mx1 = fmaxf(mx1, __shfl_xor_sync(0xffffffffu, mx1, 1));
        mx1 = fmaxf(mx1, __shfl_xor_sync(0xffffffffu, mx1, 2));
        float mn0 = fmaxf(m0, mx0), mn1 = fmaxf(m1, mx1);
        float al0 = __expf(m0 - mn0), al1 = __expf(m1 - mn1);
        float ls0 = 0.f, ls1 = 0.f;
#pragma unroll
        for (int nt = 0; nt < 8; nt++) {
            float e0 = __expf(s[nt][0] - mn0); s[nt][0] = e0; ls0 += e0;
            float e1 = __expf(s[nt][1] - mn0); s[nt][1] = e1; ls0 += e1;
            float e2 = __expf(s[nt][2] - mn1); s[nt][2] = e2; ls1 += e2;
            float e3 = __expf(s[nt][3] - mn1); s[nt][3] = e3; ls1 += e3;
        }
        ls0 += __shfl_xor_sync(0xffffffffu, ls0, 1);
        ls0 += __shfl_xor_sync(0xffffffffu, ls0, 2);
        ls1 += __shfl_xor_sync(0xffffffffu, ls1, 1);
        ls1 += __shfl_xor_sync(0xffffffffu, ls1, 2);
        l0 = l0*al0 + ls0; m0 = mn0;
        l1 = l1*al1 + ls1; m1 = mn1;

#pragma unroll
        for (int nt = 0; nt < 8; nt++) {
            float p0 = s[nt][0], p1 = s[nt][1], p2 = s[nt][2], p3 = s[nt][3];
            unsigned h0 = f2tf(p0), h1 = f2tf(p1), h2 = f2tf(p2), h3 = f2tf(p3);
            int c = nt*8 + t4*2;
            *(float2*)(Ph + lr0*68 + c) = make_float2(__uint_as_float(h0), __uint_as_float(h1));
            *(float2*)(Ph + lr1*68 + c) = make_float2(__uint_as_float(h2), __uint_as_float(h3));
            *(float2*)(Pl + lr0*68 + c) = make_float2(
                __uint_as_float(f2tf(p0 - __uint_as_float(h0))),
                __uint_as_float(f2tf(p1 - __uint_as_float(h1))));
            *(float2*)(Pl + lr1*68 + c) = make_float2(
                __uint_as_float(f2tf(p2 - __uint_as_float(h2))),
                __uint_as_float(f2tf(p3 - __uint_as_float(h3))));
            o[nt][0] *= al0; o[nt][1] *= al0;
            o[nt][2] *= al1; o[nt][3] *= al1;
        }
        __syncthreads();

#pragma unroll
        for (int kb = 0; kb < 8; kb++) {
            int arow = lr0*68 + kb*8 + t4;
            unsigned ah[4], al2[4];
            ah[0] = __float_as_uint(Ph[arow]);
            ah[1] = __float_as_uint(Ph[arow + 8*68]);
            ah[2] = __float_as_uint(Ph[arow + 4]);
            ah[3] = __float_as_uint(Ph[arow + 8*68 + 4]);
            al2[0] = __float_as_uint(Pl[arow]);
            al2[1] = __float_as_uint(Pl[arow + 8*68]);
            al2[2] = __float_as_uint(Pl[arow + 4]);
            al2[3] = __float_as_uint(Pl[arow + 8*68 + 4]);
            int krow = (kb*8 + t4)*72;
#pragma unroll
            for (int nt = 0; nt < 8; nt++) {
                int bcol = nt*8 + gp;
                unsigned bh0 = __float_as_uint(Vh[krow + bcol]);
                unsigned bh1 = __float_as_uint(Vh[krow + 4*72 + bcol]);
                unsigned bl0 = __float_as_uint(Vl[krow + bcol]);
                unsigned bl1 = __float_as_uint(Vl[krow + 4*72 + bcol]);
                mma_tf32(o[nt], ah, bh0, bh1);
                mma_tf32(o[nt], ah, bl0, bl1);
                mma_tf32(o[nt], al2, bh0, bh1);
            }
        }
    }
    // epilogue: attn*sigmoid(gate), written in place to G
    float inv0 = 1.f / l0, inv1 = 1.f / l1;
    size_t ob0 = ((size_t)(b*S_ + qt*128 + lr0))*(H_*HD_) + h*HD_;
    size_t ob1 = ((size_t)(b*S_ + qt*128 + lr1))*(H_*HD_) + h*HD_;
#pragma unroll
    for (int nt = 0; nt < 8; nt++) {
        int c = nt*8 + t4*2;
        float2 gv0 = *(float2*)(G + ob0 + c);
        float2 gv1 = *(float2*)(G + ob1 + c);
        float2 r0, r1;
        r0.x = o[nt][0]*inv0 / (1.f + __expf(-gv0.x));
        r0.y = o[nt][1]*inv0 / (1.f + __expf(-gv0.y));
        r1.x = o[nt][2]*inv1 / (1.f + __expf(-gv1.x));
        r1.y = o[nt][3]*inv1 / (1.f + __expf(-gv1.y));
        *(float2*)(G + ob0 + c) = r0;
        *(float2*)(G + ob1 + c) = r1;
    }
}

// ======= elementwise =======
__global__ void silumul_kernel() {
    size_t i = (size_t)blockIdx.x * 256 + threadIdx.x;
    float4 a = ((float4*)g_h)[i];
    float4 b = ((float4*)g_h3)[i];
    a.x = a.x / (1.f + __expf(-a.x)) * b.x;
    a.y = a.y / (1.f + __expf(-a.y)) * b.y;
    a.z = a.z / (1.f + __expf(-a.z)) * b.z;
    a.w = a.w / (1.f + __expf(-a.w)) * b.w;
    ((float4*)g_h)[i] = a;
}

// ======= router + moe bookkeeping =======
__global__ void router_kernel(const float* __restrict__ rw) {
    int t = blockIdx.x;
    const float* x = g_xn2 + (size_t)t * D_;
    float le[8] = {0,0,0,0,0,0,0,0};
    for (int d = threadIdx.x; d < D_; d += 256) {
        float xv = x[d];
        const float4* r4 = (const float4*)(rw + (size_t)d * 8);
        float4 aa = r4[0], bb = r4[1];
        le[0] += xv*aa.x; le[1] += xv*aa.y; le[2] += xv*aa.z; le[3] += xv*aa.w;
        le[4] += xv*bb.x; le[5] += xv*bb.y; le[6] += xv*bb.z; le[7] += xv*bb.w;
    }
#pragma unroll
    for (int e = 0; e < 8; e++)
        for (int o = 16; o > 0; o >>= 1)
            le[e] += __shfl_xor_sync(0xffffffffu, le[e], o);
    __shared__ float smr[8][8];
    if ((threadIdx.x & 31) == 0)
#pragma unroll
        for (int e = 0; e < 8; e++) smr[threadIdx.x >> 5][e] = le[e];
    __syncthreads();
    if (threadIdx.x == 0) {
        float lg[8];
#pragma unroll
        for (int e = 0; e < 8; e++) {
            float s = 0.f;
            for (int w2 = 0; w2 < 8; w2++) s += smr[w2][e];
            lg[e] = s;
        }
        float mx = lg[0];
        for (int e = 1; e < 8; e++) mx = fmaxf(mx, lg[e]);
        float p[8], s = 0.f;
        for (int e = 0; e < 8; e++) { p[e] = expf(lg[e] - mx); s += p[e]; }
        float invs = 1.f / s;
        for (int e = 0; e < 8; e++) { p[e] *= invs; atomicAdd(&g_probsum[e], p[e]); }
        int i0 = 0;
        for (int e = 1; e < 8; e++) if (p[e] > p[i0]) i0 = e;
        int i1 = (i0 == 0) ? 1 : 0;
        for (int e = 0; e < 8; e++) if (e != i0 && p[e] > p[i1]) i1 = e;
        float tv0 = p[i0], tv1 = p[i1], s2 = tv0 + tv1;
        g_topi[t*2] = i0; g_topi[t*2+1] = i1;
        g_topv[t*2] = tv0/s2; g_topv[t*2+1] = tv1/s2;
        atomicAdd(&g_counts[i0], 1);
        atomicAdd(&g_counts[i1], 1);
    }
}
__global__ void zero_kernel() {
    int t = threadIdx.x;
    if (t < E_) { g_counts[t] = 0; g_cursor[t] = 0; g_probsum[t] = 0.f; }
}
__global__ void offsets_aux_kernel(float* __restrict__ aux_out) {
    if (threadIdx.x == 0) {
        int o = 0;
        for (int e = 0; e < E_; e++) { g_off[e] = o; o += g_counts[e]; }
        g_off[E_] = o;
        float aux = 0.f;
        for (int e = 0; e < E_; e++)
            aux += ((float)g_counts[e] / (NTOK*2.0f)) * (g_probsum[e] / (float)NTOK);
        aux_out[0] = 0.01f * (float)E_ * aux;
    }
}
__global__ void scatter_kernel() {
    int t = blockIdx.x * 256 + threadIdx.x;
    if (t >= NTOK) return;
#pragma unroll
    for (int k2 = 0; k2 < 2; k2++) {
        int e = g_topi[t*2+k2];
        int pos = g_off[e] + atomicAdd(&g_cursor[e], 1);
        g_permTok[pos] = t;
        g_permW[pos] = g_topv[t*2+k2];
        g_tokSlot[t*2+k2] = pos;
    }
}
__global__ void finaladd_kernel(float* __restrict__ out) {
    size_t i = (size_t)blockIdx.x * 256 + threadIdx.x;
    int t = (int)(i >> 10);
    int d = (int)(i & 1023);
    int s0 = g_tokSlot[t*2], s1 = g_tokSlot[t*2+1];
    out[i] = g_x1[i] + g_tmp[(size_t)s0*D_ + d] + g_tmp[(size_t)s1*D_ + d];
}

// ======= host launcher =======
extern "C" void kernel_launch(void* const* d_in, const int* in_sizes, int n_in,
                              void* d_out, int out_size) {
    const float* x        = (const float*)d_in[0];
    const float* attn_nw  = (const float*)d_in[1];
    const float* ffn_nw   = (const float*)d_in[2];
    const float* q_nw     = (const float*)d_in[3];
    const float* k_nw     = (const float*)d_in[4];
    const float* wq       = (const float*)d_in[5];
    const float* wk       = (const float*)d_in[6];
    const float* wv       = (const float*)d_in[7];
    const float* wo       = (const float*)d_in[8];
    const float* wg       = (const float*)d_in[9];
    const float* router_w = (const float*)d_in[10];
    const float* w1       = (const float*)d_in[11];
    const float* w3       = (const float*)d_in[12];
    const float* w2       = (const float*)d_in[13];
    float* out = (float*)d_out;

    float *p_xn, *p_q, *p_k, *p_v, *p_gate, *p_x1, *p_xn2;
    cudaGetSymbolAddress((void**)&p_xn, g_xn);
    cudaGetSymbolAddress((void**)&p_q, g_q);
    cudaGetSymbolAddress((void**)&p_k, g_k);
    cudaGetSymbolAddress((void**)&p_v, g_v);
    cudaGetSymbolAddress((void**)&p_gate, g_gate);
    cudaGetSymbolAddress((void**)&p_x1, g_x1);
    cudaGetSymbolAddress((void**)&p_xn2, g_xn2);

    cudaFuncSetAttribute(proj_gemm, cudaFuncAttributeMaxDynamicSharedMemorySize, SMEM_GEMM_S);
    cudaFuncSetAttribute(gemm_plain<1,true>, cudaFuncAttributeMaxDynamicSharedMemorySize, SMEM_GEMM_S);
    cudaFuncSetAttribute(moe13_gemm, cudaFuncAttributeMaxDynamicSharedMemorySize, SMEM_GEMM);
    cudaFuncSetAttribute(moe2_gemm, cudaFuncAttributeMaxDynamicSharedMemorySize, SMEM_GEMM);
    cudaFuncSetAttribute(attn_tc2, cudaFuncAttributeMaxDynamicSharedMemorySize, SMEM_ATTN3);

    rmsnorm_kernel<<<NTOK, 256>>>(x, attn_nw, p_xn, 1e-6f);
    proj_gemm<<<dim3(20,32), 256, SMEM_GEMM_S>>>(wq, wk, wv, wg);
    qkrope_kernel<<<(NTOK*H_*32)/256, 256>>>(p_q, q_nw, H_);
    qkrope_kernel<<<(NTOK*KH_*32)/256, 256>>>(p_k, k_nw, KH_);
    attn_tc2<<<dim3(S_/128, H_, B_), 256, SMEM_ATTN3>>>(p_q, p_k, p_v, p_gate);
    gemm_plain<1,true><<<dim3(8,32), 256, SMEM_GEMM_S>>>(p_gate, wo, p_x1, x, 1024, 1024, NTOK);
    rmsnorm_kernel<<<NTOK, 256>>>(p_x1, ffn_nw, p_xn2, 1e-6f);
    zero_kernel<<<1, 32>>>();
    router_kernel<<<NTOK, 256>>>(router_w);
    offsets_aux_kernel<<<1, 32>>>(out + (size_t)NTOK*D_);
    scatter_kernel<<<NTOK/256, 256>>>();
    moe13_gemm<<<dim3(FF_/128, 32, 16), 256, SMEM_GEMM>>>(w1, w3);
    silumul_kernel<<<((size_t)NSLOT*FF_/4)/256, 256>>>();
    moe2_gemm<<<dim3(D_/128, 32, 8), 256, SMEM_GEMM>>>(w2);
    finaladd_kernel<<<(NTOK*1024)/256, 256>>>(out);
}